// round 2
// baseline (speedup 1.0000x reference)
#include <cuda_runtime.h>
#include <cstdint>
#include <cstring>

typedef unsigned long long ull;

#define DD      512
#define MM      64
#define TOK     128
#define KC      32
#define SHRINK_C 0.0025f
#define EPSV     1e-12f
#define NS_MAX   16

// ---------------- scratch (device globals; no allocation allowed) ----------------
__device__ float    g_ST[(size_t)MM * 65536];        // scores transposed [M][N]
__device__ unsigned g_colmax[MM];                    // order-monotone encoded float max
__device__ float    g_pZ[MM * NS_MAX];
__device__ float    g_pL1[MM * NS_MAX];
__device__ float    g_pvec[(size_t)MM * NS_MAX * DD];

// ---------------- helpers ----------------
__device__ __forceinline__ unsigned encf(float f) {
    unsigned u = __float_as_uint(f);
    return (u & 0x80000000u) ? ~u : (u | 0x80000000u);
}
__device__ __forceinline__ float decf(unsigned u) {
    return (u & 0x80000000u) ? __uint_as_float(u & 0x7FFFFFFFu) : __uint_as_float(~u);
}
__device__ __forceinline__ ull bcast2(float x) {
    ull r; unsigned b = __float_as_uint(x);
    asm("mov.b64 %0, {%1, %1};" : "=l"(r) : "r"(b));
    return r;
}
__device__ __forceinline__ void ffma2(ull& d, ull a, ull b) {
    asm("fma.rn.f32x2 %0, %1, %2, %0;" : "+l"(d) : "l"(a), "l"(b));
}
__device__ __forceinline__ float2 unpack2(ull v) {
    unsigned lo, hi;
    asm("mov.b64 {%0, %1}, %2;" : "=r"(lo), "=r"(hi) : "l"(v));
    float2 f; f.x = __uint_as_float(lo); f.y = __uint_as_float(hi);
    return f;
}

// ---------------- K1 shared layout ----------------
struct K1Smem {
    float Qt[KC][TOK + 2];     // q tile transposed, token-contiguous (pairs via LDS.64)
    float Mem1[KC][MM + 1];    // mem tile, k-major
    float S[TOK][MM + 1];      // raw scores
    float At[MM][TOK + 2];     // attn values, token-contiguous
    float M2[MM][66];          // mem d-chunk for GEMM2
    float pmax[4][MM];         // per-block column-max partials
};

// ---------------- K0: init ----------------
__global__ void k0_init() {
    if (threadIdx.x < MM) g_colmax[threadIdx.x] = 0u;  // below all encodings
}

// ---------------- K1: scores + read path ----------------
__global__ __launch_bounds__(256) void k1_main(
    const float* __restrict__ qg, const float* __restrict__ memg,
    float* __restrict__ outO, float* __restrict__ outA, int N)
{
    extern __shared__ char smraw[];
    K1Smem& sm = *reinterpret_cast<K1Smem*>(smraw);
    const int tid = threadIdx.x;
    const int tx = tid & 15;        // m-group: m = tx*4 + j
    const int ty = tid >> 4;        // token-group: t = ty*8 + (0..7)
    const int n0 = blockIdx.x * TOK;
    const int t0 = ty * 8;
    const int m0 = tx * 4;

    // ===== GEMM1: S[t][m] = sum_k q[n0+t][k] * mem[m][k], f32x2 token-pairs =====
    ull acc[4][4];
    #pragma unroll
    for (int r = 0; r < 4; r++)
        #pragma unroll
        for (int j = 0; j < 4; j++) acc[r][j] = 0ull;

    for (int kc = 0; kc < DD / KC; kc++) {
        for (int idx = tid; idx < TOK * KC; idx += 256) {
            int t = idx >> 5, kk = idx & 31;
            sm.Qt[kk][t] = qg[(size_t)(n0 + t) * DD + kc * KC + kk];
        }
        for (int idx = tid; idx < MM * KC; idx += 256) {
            int m = idx >> 5, kk = idx & 31;
            sm.Mem1[kk][m] = memg[m * DD + kc * KC + kk];
        }
        __syncthreads();
        #pragma unroll 8
        for (int k = 0; k < KC; k++) {
            ull qa[4], bb[4];
            #pragma unroll
            for (int r = 0; r < 4; r++)
                qa[r] = *reinterpret_cast<const ull*>(&sm.Qt[k][t0 + 2 * r]);
            #pragma unroll
            for (int j = 0; j < 4; j++)
                bb[j] = bcast2(sm.Mem1[k][m0 + j]);
            #pragma unroll
            for (int r = 0; r < 4; r++)
                #pragma unroll
                for (int j = 0; j < 4; j++)
                    ffma2(acc[r][j], qa[r], bb[j]);
        }
        __syncthreads();
    }

    // stage scores to smem
    #pragma unroll
    for (int r = 0; r < 4; r++)
        #pragma unroll
        for (int j = 0; j < 4; j++) {
            float2 v = unpack2(acc[r][j]);
            sm.S[t0 + 2 * r][m0 + j]     = v.x;
            sm.S[t0 + 2 * r + 1][m0 + j] = v.y;
        }
    __syncthreads();

    // ===== column path: write S^T scratch + per-m max =====
    {
        int m = tid & 63, c = tid >> 6;         // c in [0,4): 32 tokens each
        float mx = -3.4e38f;
        size_t base = (size_t)m * N + n0 + c * 32;
        #pragma unroll
        for (int i = 0; i < 32; i += 4) {
            float a0 = sm.S[c * 32 + i + 0][m];
            float a1 = sm.S[c * 32 + i + 1][m];
            float a2 = sm.S[c * 32 + i + 2][m];
            float a3 = sm.S[c * 32 + i + 3][m];
            mx = fmaxf(mx, fmaxf(fmaxf(a0, a1), fmaxf(a2, a3)));
            *reinterpret_cast<float4*>(&g_ST[base + i]) = make_float4(a0, a1, a2, a3);
        }
        sm.pmax[c][m] = mx;
    }
    __syncthreads();
    if (tid < MM) {
        float mx = fmaxf(fmaxf(sm.pmax[0][tid], sm.pmax[1][tid]),
                         fmaxf(sm.pmax[2][tid], sm.pmax[3][tid]));
        atomicMax(&g_colmax[tid], encf(mx));
    }

    // ===== row path: softmax over M, shrink, L1 normalize, write attn =====
    if (tid < TOK) {
        int t = tid;
        float mx = -3.4e38f;
        for (int m = 0; m < MM; m++) mx = fmaxf(mx, sm.S[t][m]);
        float z = 0.f;
        for (int m = 0; m < MM; m++) {
            float e = __expf(sm.S[t][m] - mx);
            sm.At[m][t] = e; z += e;
        }
        float invz = 1.0f / z;
        float l1 = 0.f;
        for (int m = 0; m < MM; m++) {
            float a = sm.At[m][t] * invz;
            float s2 = a - SHRINK_C;
            float ash = (s2 > 0.f) ? s2 * a / (s2 + EPSV) : 0.f;
            sm.At[m][t] = ash; l1 += ash;
        }
        float sc = 1.0f / fmaxf(l1, EPSV);
        for (int m = 0; m < MM; m += 4) {
            float v0 = sm.At[m + 0][t] * sc;
            float v1 = sm.At[m + 1][t] * sc;
            float v2 = sm.At[m + 2][t] * sc;
            float v3 = sm.At[m + 3][t] * sc;
            sm.At[m + 0][t] = v0; sm.At[m + 1][t] = v1;
            sm.At[m + 2][t] = v2; sm.At[m + 3][t] = v3;
            *reinterpret_cast<float4*>(&outA[(size_t)(n0 + t) * MM + m]) =
                make_float4(v0, v1, v2, v3);
        }
    }
    __syncthreads();

    // ===== GEMM2: add_memory[t][d] = sum_m At[t][m] * mem[m][d] (f32x2 token-pairs) =====
    for (int dc = 0; dc < DD / 64; dc++) {
        for (int idx = tid; idx < MM * 64; idx += 256) {
            int m = idx >> 6, dd = idx & 63;
            sm.M2[m][dd] = memg[m * DD + dc * 64 + dd];
        }
        __syncthreads();
        ull a2[4][4];
        #pragma unroll
        for (int r = 0; r < 4; r++)
            #pragma unroll
            for (int j = 0; j < 4; j++) a2[r][j] = 0ull;
        #pragma unroll 8
        for (int m = 0; m < MM; m++) {
            ull tp[4], bb[4];
            #pragma unroll
            for (int r = 0; r < 4; r++)
                tp[r] = *reinterpret_cast<const ull*>(&sm.At[m][t0 + 2 * r]);
            #pragma unroll
            for (int j = 0; j < 4; j++)
                bb[j] = bcast2(sm.M2[m][m0 + j]);
            #pragma unroll
            for (int r = 0; r < 4; r++)
                #pragma unroll
                for (int j = 0; j < 4; j++)
                    ffma2(a2[r][j], tp[r], bb[j]);
        }
        #pragma unroll
        for (int r = 0; r < 4; r++) {
            float2 u0 = unpack2(a2[r][0]), u1 = unpack2(a2[r][1]);
            float2 u2 = unpack2(a2[r][2]), u3 = unpack2(a2[r][3]);
            size_t rowlo = (size_t)(n0 + t0 + 2 * r) * (2 * DD) + DD + dc * 64 + m0;
            size_t rowhi = rowlo + (2 * DD);
            *reinterpret_cast<float4*>(&outO[rowlo]) = make_float4(u0.x, u1.x, u2.x, u3.x);
            *reinterpret_cast<float4*>(&outO[rowhi]) = make_float4(u0.y, u1.y, u2.y, u3.y);
        }
        __syncthreads();
    }

    // ===== q copy -> out[:, 0:512] =====
    {
        const float4* q4 = reinterpret_cast<const float4*>(qg);
        float4* o4 = reinterpret_cast<float4*>(outO);
        for (int idx = tid; idx < TOK * (DD / 4); idx += 256) {
            int t = idx >> 7, dq = idx & 127;
            o4[(size_t)(n0 + t) * (2 * DD / 4) + dq] = q4[(size_t)(n0 + t) * (DD / 4) + dq];
        }
    }
}

// ---------------- K2: partial column exp-sums ----------------
__global__ __launch_bounds__(256) void k2_colz(int N) {
    int m = blockIdx.y, s = blockIdx.x;
    float cmax = decf(g_colmax[m]);
    const float* row = g_ST + (size_t)m * N;
    float loc = 0.f;
    for (int i = threadIdx.x; i < 8192; i += 256) {
        int n = s * 8192 + i;
        if (n < N) loc += __expf(row[n] - cmax);
    }
    __shared__ float red[256];
    red[threadIdx.x] = loc; __syncthreads();
    for (int st = 128; st > 0; st >>= 1) {
        if (threadIdx.x < st) red[threadIdx.x] += red[threadIdx.x + st];
        __syncthreads();
    }
    if (threadIdx.x == 0) g_pZ[m * NS_MAX + s] = red[0];
}

// ---------------- K3: shrink + sparse vec/L1 partials ----------------
__global__ __launch_bounds__(512) void k3_sparse(const float* __restrict__ qg, int N, int NS) {
    int m = blockIdx.y, s = blockIdx.x;
    int tid = threadIdx.x;
    float cmax = decf(g_colmax[m]);
    float Z = 0.f;
    for (int j = 0; j < NS; j++) Z += g_pZ[m * NS_MAX + j];
    float invZ = 1.0f / Z;
    const float* row = g_ST + (size_t)m * N;
    __shared__ float ash_sh[512];
    float accv = 0.f, l1 = 0.f;
    for (int c = 0; c < 16; c++) {
        int n = s * 8192 + c * 512 + tid;
        float ash = 0.f;
        if (n < N) {
            float a = __expf(row[n] - cmax) * invZ;
            float s2 = a - SHRINK_C;
            if (s2 > 0.f) ash = s2 * a / (s2 + EPSV);
        }
        ash_sh[tid] = ash;
        l1 += ash;
        int any = __syncthreads_or(ash > 0.f);
        if (any) {
            int nb = s * 8192 + c * 512;
            for (int i = 0; i < 512; i++) {
                float w = ash_sh[i];
                if (w > 0.f) accv += w * qg[(size_t)(nb + i) * DD + tid];
            }
        }
        __syncthreads();
    }
    g_pvec[(size_t)(m * NS_MAX + s) * DD + tid] = accv;
    __shared__ float red[512];
    red[tid] = l1; __syncthreads();
    for (int st = 256; st > 0; st >>= 1) {
        if (tid < st) red[tid] += red[tid + st];
        __syncthreads();
    }
    if (tid == 0) g_pL1[m * NS_MAX + s] = red[0];
}

// ---------------- K4: add_mem, gate, new_mem ----------------
__global__ __launch_bounds__(512) void k4_gate(
    const float* __restrict__ memg,
    const float* __restrict__ Uw, const float* __restrict__ Ub,
    const float* __restrict__ Ww, const float* __restrict__ Wb,
    float* __restrict__ outM, int NS)
{
    int m = blockIdx.x, d = threadIdx.x;
    __shared__ float am[DD], ms[DD];
    float v = 0.f, l1 = 0.f;
    for (int j = 0; j < NS; j++) {
        v += g_pvec[(size_t)(m * NS_MAX + j) * DD + d];
        l1 += g_pL1[m * NS_MAX + j];
    }
    am[d] = v / fmaxf(l1, EPSV);
    ms[d] = memg[m * DD + d];
    __syncthreads();
    float acc = Ub[d] + Wb[d];
    const float4* uw4 = reinterpret_cast<const float4*>(Uw + (size_t)d * DD);
    const float4* ww4 = reinterpret_cast<const float4*>(Ww + (size_t)d * DD);
    const float4* am4 = reinterpret_cast<const float4*>(am);
    const float4* ms4 = reinterpret_cast<const float4*>(ms);
    #pragma unroll 4
    for (int k = 0; k < DD / 4; k++) {
        float4 u = uw4[k], w = ww4[k], a = am4[k], s = ms4[k];
        acc += s.x * u.x + s.y * u.y + s.z * u.z + s.w * u.w;
        acc += a.x * w.x + a.y * w.y + a.z * w.z + a.w * w.w;
    }
    float g = 1.0f / (1.0f + __expf(-acc));
    outM[m * DD + d] = (1.0f - g) * ms[d] + g * am[d];
}

// ---------------- launch ----------------
extern "C" void kernel_launch(void* const* d_in, const int* in_sizes, int n_in,
                              void* d_out, int out_size)
{
    const float* qg   = (const float*)d_in[0];
    const float* memg = (const float*)d_in[1];
    const float* Uw   = (const float*)d_in[2];
    const float* Ub   = (const float*)d_in[3];
    const float* Ww   = (const float*)d_in[4];
    const float* Wb   = (const float*)d_in[5];

    int N  = in_sizes[0] / DD;                 // 65536
    int NS = (N + 8191) / 8192;                // 8

    float* outO = (float*)d_out;               // [N, 2D]
    float* outA = outO + (size_t)N * 2 * DD;   // [N, M]
    float* outM = outA + (size_t)N * MM;       // [M, D]

    cudaFuncSetAttribute((const void*)k1_main,
                         cudaFuncAttributeMaxDynamicSharedMemorySize,
                         (int)sizeof(K1Smem));

    k0_init<<<1, 64>>>();
    k1_main<<<N / TOK, 256, sizeof(K1Smem)>>>(qg, memg, outO, outA, N);
    k2_colz<<<dim3(NS, MM), 256>>>(N);
    k3_sparse<<<dim3(NS, MM), 512>>>(qg, N, NS);
    k4_gate<<<MM, 512>>>(memg, Uw, Ub, Ww, Wb, outM, NS);
}

// round 3
// speedup vs baseline: 1.0090x; 1.0090x over previous
#include <cuda_runtime.h>
#include <cstdint>
#include <cstring>

typedef unsigned long long ull;

#define DD      512
#define MM      64
#define TOK     128
#define KC      32
#define SHRINK_C 0.0025f
#define EPSV     1e-12f
#define NS_MAX   16

// ---------------- scratch (device globals; no allocation allowed) ----------------
__device__ float    g_ST[(size_t)MM * 65536];        // scores transposed [M][N]
__device__ unsigned g_colmax[MM];                    // order-monotone encoded float max
__device__ float    g_pZ[MM * NS_MAX];
__device__ float    g_pL1[MM * NS_MAX];
__device__ float    g_pvec[(size_t)MM * NS_MAX * DD];

// ---------------- helpers ----------------
__device__ __forceinline__ unsigned encf(float f) {
    unsigned u = __float_as_uint(f);
    return (u & 0x80000000u) ? ~u : (u | 0x80000000u);
}
__device__ __forceinline__ float decf(unsigned u) {
    return (u & 0x80000000u) ? __uint_as_float(u & 0x7FFFFFFFu) : __uint_as_float(~u);
}
__device__ __forceinline__ ull bcast2(float x) {
    ull r; unsigned b = __float_as_uint(x);
    asm("mov.b64 %0, {%1, %1};" : "=l"(r) : "r"(b));
    return r;
}
__device__ __forceinline__ void ffma2(ull& d, ull a, ull b) {
    asm("fma.rn.f32x2 %0, %1, %2, %0;" : "+l"(d) : "l"(a), "l"(b));
}
__device__ __forceinline__ float2 unpack2(ull v) {
    unsigned lo, hi;
    asm("mov.b64 {%0, %1}, %2;" : "=r"(lo), "=r"(hi) : "l"(v));
    float2 f; f.x = __uint_as_float(lo); f.y = __uint_as_float(hi);
    return f;
}

// ---------------- K1 shared layout ----------------
struct K1Smem {
    float Qt[KC][TOK + 2];     // q tile transposed, token-contiguous (pairs via LDS.64)
    float Mem1[KC][MM + 1];    // mem tile, k-major
    float S[TOK][MM + 1];      // raw scores
    float At[MM][TOK + 2];     // attn values, token-contiguous
    float M2[MM][66];          // mem d-chunk for GEMM2
    float pmax[4][MM];         // per-block column-max partials
};

// ---------------- K0: init ----------------
__global__ void k0_init() {
    if (threadIdx.x < MM) g_colmax[threadIdx.x] = 0u;  // below all encodings
}

// ---------------- K1: scores + read path ----------------
__global__ __launch_bounds__(256) void k1_main(
    const float* __restrict__ qg, const float* __restrict__ memg,
    float* __restrict__ outO, float* __restrict__ outA, int N)
{
    extern __shared__ char smraw[];
    K1Smem& sm = *reinterpret_cast<K1Smem*>(smraw);
    const int tid = threadIdx.x;
    const int tx = tid & 15;        // m-group: m = tx*4 + j
    const int ty = tid >> 4;        // token-group: t = ty*8 + (0..7)
    const int n0 = blockIdx.x * TOK;
    const int t0 = ty * 8;
    const int m0 = tx * 4;

    // ===== GEMM1: S[t][m] = sum_k q[n0+t][k] * mem[m][k], f32x2 token-pairs =====
    ull acc[4][4];
    #pragma unroll
    for (int r = 0; r < 4; r++)
        #pragma unroll
        for (int j = 0; j < 4; j++) acc[r][j] = 0ull;

    for (int kc = 0; kc < DD / KC; kc++) {
        for (int idx = tid; idx < TOK * KC; idx += 256) {
            int t = idx >> 5, kk = idx & 31;
            sm.Qt[kk][t] = qg[(size_t)(n0 + t) * DD + kc * KC + kk];
        }
        for (int idx = tid; idx < MM * KC; idx += 256) {
            int m = idx >> 5, kk = idx & 31;
            sm.Mem1[kk][m] = memg[m * DD + kc * KC + kk];
        }
        __syncthreads();
        #pragma unroll 8
        for (int k = 0; k < KC; k++) {
            ull qa[4], bb[4];
            #pragma unroll
            for (int r = 0; r < 4; r++)
                qa[r] = *reinterpret_cast<const ull*>(&sm.Qt[k][t0 + 2 * r]);
            #pragma unroll
            for (int j = 0; j < 4; j++)
                bb[j] = bcast2(sm.Mem1[k][m0 + j]);
            #pragma unroll
            for (int r = 0; r < 4; r++)
                #pragma unroll
                for (int j = 0; j < 4; j++)
                    ffma2(acc[r][j], qa[r], bb[j]);
        }
        __syncthreads();
    }

    // stage scores to smem
    #pragma unroll
    for (int r = 0; r < 4; r++)
        #pragma unroll
        for (int j = 0; j < 4; j++) {
            float2 v = unpack2(acc[r][j]);
            sm.S[t0 + 2 * r][m0 + j]     = v.x;
            sm.S[t0 + 2 * r + 1][m0 + j] = v.y;
        }
    __syncthreads();

    // ===== column path: write S^T scratch + per-m max =====
    {
        int m = tid & 63, c = tid >> 6;         // c in [0,4): 32 tokens each
        float mx = -3.4e38f;
        size_t base = (size_t)m * N + n0 + c * 32;
        #pragma unroll
        for (int i = 0; i < 32; i += 4) {
            float a0 = sm.S[c * 32 + i + 0][m];
            float a1 = sm.S[c * 32 + i + 1][m];
            float a2 = sm.S[c * 32 + i + 2][m];
            float a3 = sm.S[c * 32 + i + 3][m];
            mx = fmaxf(mx, fmaxf(fmaxf(a0, a1), fmaxf(a2, a3)));
            *reinterpret_cast<float4*>(&g_ST[base + i]) = make_float4(a0, a1, a2, a3);
        }
        sm.pmax[c][m] = mx;
    }
    __syncthreads();
    if (tid < MM) {
        float mx = fmaxf(fmaxf(sm.pmax[0][tid], sm.pmax[1][tid]),
                         fmaxf(sm.pmax[2][tid], sm.pmax[3][tid]));
        atomicMax(&g_colmax[tid], encf(mx));
    }

    // ===== row path: softmax over M, shrink, L1 normalize, write attn =====
    if (tid < TOK) {
        int t = tid;
        float mx = -3.4e38f;
        for (int m = 0; m < MM; m++) mx = fmaxf(mx, sm.S[t][m]);
        float z = 0.f;
        for (int m = 0; m < MM; m++) {
            float e = __expf(sm.S[t][m] - mx);
            sm.At[m][t] = e; z += e;
        }
        float invz = 1.0f / z;
        float l1 = 0.f;
        for (int m = 0; m < MM; m++) {
            float a = sm.At[m][t] * invz;
            float s2 = a - SHRINK_C;
            float ash = (s2 > 0.f) ? s2 * a / (s2 + EPSV) : 0.f;
            sm.At[m][t] = ash; l1 += ash;
        }
        float sc = 1.0f / fmaxf(l1, EPSV);
        for (int m = 0; m < MM; m += 4) {
            float v0 = sm.At[m + 0][t] * sc;
            float v1 = sm.At[m + 1][t] * sc;
            float v2 = sm.At[m + 2][t] * sc;
            float v3 = sm.At[m + 3][t] * sc;
            sm.At[m + 0][t] = v0; sm.At[m + 1][t] = v1;
            sm.At[m + 2][t] = v2; sm.At[m + 3][t] = v3;
            *reinterpret_cast<float4*>(&outA[(size_t)(n0 + t) * MM + m]) =
                make_float4(v0, v1, v2, v3);
        }
    }
    __syncthreads();

    // ===== GEMM2: add_memory[t][d] = sum_m At[t][m] * mem[m][d] (f32x2 token-pairs) =====
    for (int dc = 0; dc < DD / 64; dc++) {
        for (int idx = tid; idx < MM * 64; idx += 256) {
            int m = idx >> 6, dd = idx & 63;
            sm.M2[m][dd] = memg[m * DD + dc * 64 + dd];
        }
        __syncthreads();
        ull a2[4][4];
        #pragma unroll
        for (int r = 0; r < 4; r++)
            #pragma unroll
            for (int j = 0; j < 4; j++) a2[r][j] = 0ull;
        #pragma unroll 8
        for (int m = 0; m < MM; m++) {
            ull tp[4], bb[4];
            #pragma unroll
            for (int r = 0; r < 4; r++)
                tp[r] = *reinterpret_cast<const ull*>(&sm.At[m][t0 + 2 * r]);
            #pragma unroll
            for (int j = 0; j < 4; j++)
                bb[j] = bcast2(sm.M2[m][m0 + j]);
            #pragma unroll
            for (int r = 0; r < 4; r++)
                #pragma unroll
                for (int j = 0; j < 4; j++)
                    ffma2(a2[r][j], tp[r], bb[j]);
        }
        #pragma unroll
        for (int r = 0; r < 4; r++) {
            float2 u0 = unpack2(a2[r][0]), u1 = unpack2(a2[r][1]);
            float2 u2 = unpack2(a2[r][2]), u3 = unpack2(a2[r][3]);
            size_t rowlo = (size_t)(n0 + t0 + 2 * r) * (2 * DD) + DD + dc * 64 + m0;
            size_t rowhi = rowlo + (2 * DD);
            *reinterpret_cast<float4*>(&outO[rowlo]) = make_float4(u0.x, u1.x, u2.x, u3.x);
            *reinterpret_cast<float4*>(&outO[rowhi]) = make_float4(u0.y, u1.y, u2.y, u3.y);
        }
        __syncthreads();
    }

    // ===== q copy -> out[:, 0:512] =====
    {
        const float4* q4 = reinterpret_cast<const float4*>(qg);
        float4* o4 = reinterpret_cast<float4*>(outO);
        for (int idx = tid; idx < TOK * (DD / 4); idx += 256) {
            int t = idx >> 7, dq = idx & 127;
            o4[(size_t)(n0 + t) * (2 * DD / 4) + dq] = q4[(size_t)(n0 + t) * (DD / 4) + dq];
        }
    }
}

// ---------------- K2: partial column exp-sums ----------------
__global__ __launch_bounds__(256) void k2_colz(int N) {
    int m = blockIdx.y, s = blockIdx.x;
    float cmax = decf(g_colmax[m]);
    const float* row = g_ST + (size_t)m * N;
    float loc = 0.f;
    for (int i = threadIdx.x; i < 8192; i += 256) {
        int n = s * 8192 + i;
        if (n < N) loc += __expf(row[n] - cmax);
    }
    __shared__ float red[256];
    red[threadIdx.x] = loc; __syncthreads();
    for (int st = 128; st > 0; st >>= 1) {
        if (threadIdx.x < st) red[threadIdx.x] += red[threadIdx.x + st];
        __syncthreads();
    }
    if (threadIdx.x == 0) g_pZ[m * NS_MAX + s] = red[0];
}

// ---------------- K3: shrink + sparse vec/L1 partials ----------------
__global__ __launch_bounds__(512) void k3_sparse(const float* __restrict__ qg, int N, int NS) {
    int m = blockIdx.y, s = blockIdx.x;
    int tid = threadIdx.x;
    float cmax = decf(g_colmax[m]);
    float Z = 0.f;
    for (int j = 0; j < NS; j++) Z += g_pZ[m * NS_MAX + j];
    float invZ = 1.0f / Z;
    const float* row = g_ST + (size_t)m * N;
    __shared__ float ash_sh[512];
    float accv = 0.f, l1 = 0.f;
    for (int c = 0; c < 16; c++) {
        int n = s * 8192 + c * 512 + tid;
        float ash = 0.f;
        if (n < N) {
            float a = __expf(row[n] - cmax) * invZ;
            float s2 = a - SHRINK_C;
            if (s2 > 0.f) ash = s2 * a / (s2 + EPSV);
        }
        ash_sh[tid] = ash;
        l1 += ash;
        int any = __syncthreads_or(ash > 0.f);
        if (any) {
            int nb = s * 8192 + c * 512;
            for (int i = 0; i < 512; i++) {
                float w = ash_sh[i];
                if (w > 0.f) accv += w * qg[(size_t)(nb + i) * DD + tid];
            }
        }
        __syncthreads();
    }
    g_pvec[(size_t)(m * NS_MAX + s) * DD + tid] = accv;
    __shared__ float red[512];
    red[tid] = l1; __syncthreads();
    for (int st = 256; st > 0; st >>= 1) {
        if (tid < st) red[tid] += red[tid + st];
        __syncthreads();
    }
    if (tid == 0) g_pL1[m * NS_MAX + s] = red[0];
}

// ---------------- K4: add_mem, gate, new_mem ----------------
__global__ __launch_bounds__(512) void k4_gate(
    const float* __restrict__ memg,
    const float* __restrict__ Uw, const float* __restrict__ Ub,
    const float* __restrict__ Ww, const float* __restrict__ Wb,
    float* __restrict__ outM, int NS)
{
    int m = blockIdx.x, d = threadIdx.x;
    __shared__ float am[DD], ms[DD];
    float v = 0.f, l1 = 0.f;
    for (int j = 0; j < NS; j++) {
        v += g_pvec[(size_t)(m * NS_MAX + j) * DD + d];
        l1 += g_pL1[m * NS_MAX + j];
    }
    am[d] = v / fmaxf(l1, EPSV);
    ms[d] = memg[m * DD + d];
    __syncthreads();
    float acc = Ub[d] + Wb[d];
    const float4* uw4 = reinterpret_cast<const float4*>(Uw + (size_t)d * DD);
    const float4* ww4 = reinterpret_cast<const float4*>(Ww + (size_t)d * DD);
    const float4* am4 = reinterpret_cast<const float4*>(am);
    const float4* ms4 = reinterpret_cast<const float4*>(ms);
    #pragma unroll 4
    for (int k = 0; k < DD / 4; k++) {
        float4 u = uw4[k], w = ww4[k], a = am4[k], s = ms4[k];
        acc += s.x * u.x + s.y * u.y + s.z * u.z + s.w * u.w;
        acc += a.x * w.x + a.y * w.y + a.z * w.z + a.w * w.w;
    }
    float g = 1.0f / (1.0f + __expf(-acc));
    outM[m * DD + d] = (1.0f - g) * ms[d] + g * am[d];
}

// ---------------- launch ----------------
extern "C" void kernel_launch(void* const* d_in, const int* in_sizes, int n_in,
                              void* d_out, int out_size)
{
    const float* qg   = (const float*)d_in[0];
    const float* memg = (const float*)d_in[1];
    const float* Uw   = (const float*)d_in[2];
    const float* Ub   = (const float*)d_in[3];
    const float* Ww   = (const float*)d_in[4];
    const float* Wb   = (const float*)d_in[5];

    int N  = in_sizes[0] / DD;                 // 65536
    int NS = (N + 8191) / 8192;                // 8

    float* outO = (float*)d_out;               // [N, 2D]
    float* outA = outO + (size_t)N * 2 * DD;   // [N, M]
    float* outM = outA + (size_t)N * MM;       // [M, D]

    cudaFuncSetAttribute((const void*)k1_main,
                         cudaFuncAttributeMaxDynamicSharedMemorySize,
                         (int)sizeof(K1Smem));

    k0_init<<<1, 64>>>();
    k1_main<<<N / TOK, 256, sizeof(K1Smem)>>>(qg, memg, outO, outA, N);
    k2_colz<<<dim3(NS, MM), 256>>>(N);
    k3_sparse<<<dim3(NS, MM), 512>>>(qg, N, NS);
    k4_gate<<<MM, 512>>>(memg, Uw, Ub, Ww, Wb, outM, NS);
}

// round 6
// speedup vs baseline: 1.5129x; 1.4993x over previous
#include <cuda_runtime.h>
#include <cstdint>

#define DD 512
#define MM 64
#define TOK 128
#define SHRINK_C 0.0025f
#define EPSV 1e-12f
#define NS_MAX 16

__device__ float    g_ST[(size_t)MM * 65536];
__device__ unsigned g_colmax[MM];
__device__ float    g_pZ[MM * NS_MAX];
__device__ float    g_pL1[MM * NS_MAX];
__device__ float    g_pvec[(size_t)MM * NS_MAX * DD];

// smem offsets (bytes). ATH/ATL alias QH/QL; MTH/MTL alias MH/ML.
#define SM_PMAX 1024
#define SM_QH   2048
#define SM_QL   18432
#define SM_MH   34816
#define SM_ML   43008
#define SM_ST   51200
#define SMEM_TOTAL 84992

__device__ __forceinline__ uint32_t s2u(const void* p) {
    uint32_t a;
    asm("{ .reg .u64 t; cvta.to.shared.u64 t, %1; cvt.u32.u64 %0, t; }" : "=r"(a) : "l"(p));
    return a;
}
__device__ __forceinline__ uint32_t swz(uint32_t b) { return b ^ ((b >> 3) & 0x70u); }
__device__ __forceinline__ uint32_t prmt_hi(float a, float b) {
    uint32_t r;
    asm("prmt.b32 %0, %1, %2, 0x7632;" : "=r"(r) : "r"(__float_as_uint(a)), "r"(__float_as_uint(b)));
    return r;
}
__device__ __forceinline__ uint32_t packlo(float a, float b) {
    float ha = __uint_as_float(__float_as_uint(a) & 0xffff0000u);
    float hb = __uint_as_float(__float_as_uint(b) & 0xffff0000u);
    float la = a - ha, lb = b - hb;
    uint32_t r;
    asm("cvt.rn.bf16x2.f32 %0, %1, %2;" : "=r"(r) : "f"(lb), "f"(la));
    return r;
}
__device__ __forceinline__ void ldsm4(uint32_t* r, uint32_t addr) {
    asm volatile("ldmatrix.sync.aligned.m8n8.x4.shared.b16 {%0,%1,%2,%3}, [%4];"
        : "=r"(r[0]), "=r"(r[1]), "=r"(r[2]), "=r"(r[3]) : "r"(addr));
}
__device__ __forceinline__ void mma16816(float* d, const uint32_t* a, const uint32_t* b) {
    asm volatile("mma.sync.aligned.m16n8k16.row.col.f32.bf16.bf16.f32 "
        "{%0,%1,%2,%3}, {%4,%5,%6,%7}, {%8,%9}, {%0,%1,%2,%3};"
        : "+f"(d[0]), "+f"(d[1]), "+f"(d[2]), "+f"(d[3])
        : "r"(a[0]), "r"(a[1]), "r"(a[2]), "r"(a[3]), "r"(b[0]), "r"(b[1]));
}

// 16 tokens x 64 cols x 64 k, 3-term hi/lo split. A rows at T0.., B rows 0..63.
__device__ __forceinline__ void gemm_tile(uint32_t sb, uint32_t AH, uint32_t AL,
        uint32_t BH, uint32_t BL, int T0, int lane, float (*acc)[4])
{
    const int tile = lane >> 3, r = lane & 7;
    const uint32_t a_base = (uint32_t)(T0 + ((tile & 1) << 3) + r) * 128u + (uint32_t)((tile >> 1) << 4);
    const uint32_t b_rr = (uint32_t)(((tile >> 1) << 3) + r);
    const uint32_t b_kb0 = (uint32_t)((tile & 1) << 4);
    #pragma unroll
    for (int s = 0; s < 4; s++) {
        uint32_t ah[4], al[4];
        uint32_t aoff = swz(a_base + (uint32_t)s * 32u);
        ldsm4(ah, sb + AH + aoff);
        ldsm4(al, sb + AL + aoff);
        #pragma unroll
        for (int g = 0; g < 4; g++) {
            uint32_t bh[4], bl[4];
            uint32_t boff = swz(((uint32_t)g * 16u + b_rr) * 128u + (uint32_t)s * 32u + b_kb0);
            ldsm4(bh, sb + BH + boff);
            ldsm4(bl, sb + BL + boff);
            mma16816(acc[2 * g],     ah, bh);
            mma16816(acc[2 * g + 1], ah, bh + 2);
            mma16816(acc[2 * g],     ah, bl);
            mma16816(acc[2 * g + 1], ah, bl + 2);
            mma16816(acc[2 * g],     al, bh);
            mma16816(acc[2 * g + 1], al, bh + 2);
        }
    }
}

__device__ __forceinline__ unsigned encf(float f) {
    unsigned u = __float_as_uint(f);
    return (u & 0x80000000u) ? ~u : (u | 0x80000000u);
}
__device__ __forceinline__ float decf(unsigned u) {
    return (u & 0x80000000u) ? __uint_as_float(u & 0x7FFFFFFFu) : __uint_as_float(~u);
}

__global__ void k0_init() {
    if (threadIdx.x < MM) g_colmax[threadIdx.x] = 0u;
}

__global__ __launch_bounds__(256, 2) void k1_main(
    const float* __restrict__ qg, const float* __restrict__ memg,
    float* __restrict__ outO, float* __restrict__ outA, int N)
{
    extern __shared__ char smc[];
    const uint32_t sb = s2u(smc);
    const int tid = threadIdx.x, wid = tid >> 5, lane = tid & 31;
    const int n0 = blockIdx.x * TOK;
    const int T0 = wid * 16;
    float* St = (float*)(smc + SM_ST);

    // ========== GEMM1: S[128 tok][64 m] over 8 k-chunks of 64 ==========
    float acc[8][4];
    #pragma unroll
    for (int i = 0; i < 8; i++)
        #pragma unroll
        for (int j = 0; j < 4; j++) acc[i][j] = 0.f;

    for (int c = 0; c < 8; c++) {
        if (c > 0) __syncthreads();   // previous mma done before overwrite
        {   // q chunk [128 tok][64 k] -> bf16 hi/lo SW128
            int t = tid >> 1, h = tid & 1;
            const float4* src = (const float4*)(qg + (size_t)(n0 + t) * DD + c * 64 + h * 32);
            uint32_t rowb = (uint32_t)t * 128u + (uint32_t)h * 64u;
            #pragma unroll
            for (int g = 0; g < 4; g++) {
                float4 f0 = src[2 * g], f1 = src[2 * g + 1];
                uint32_t off = swz(rowb + 16u * g);
                *(uint4*)(smc + SM_QH + off) = make_uint4(prmt_hi(f0.x, f0.y), prmt_hi(f0.z, f0.w),
                                                          prmt_hi(f1.x, f1.y), prmt_hi(f1.z, f1.w));
                *(uint4*)(smc + SM_QL + off) = make_uint4(packlo(f0.x, f0.y), packlo(f0.z, f0.w),
                                                          packlo(f1.x, f1.y), packlo(f1.z, f1.w));
            }
        }
        {   // mem chunk [64 m][64 k]
            int m = tid >> 2, q4 = tid & 3;
            const float4* src = (const float4*)(memg + (size_t)m * DD + c * 64 + q4 * 16);
            uint32_t rowb = (uint32_t)m * 128u + (uint32_t)q4 * 32u;
            #pragma unroll
            for (int g = 0; g < 2; g++) {
                float4 f0 = src[2 * g], f1 = src[2 * g + 1];
                uint32_t off = swz(rowb + 16u * g);
                *(uint4*)(smc + SM_MH + off) = make_uint4(prmt_hi(f0.x, f0.y), prmt_hi(f0.z, f0.w),
                                                          prmt_hi(f1.x, f1.y), prmt_hi(f1.z, f1.w));
                *(uint4*)(smc + SM_ML + off) = make_uint4(packlo(f0.x, f0.y), packlo(f0.z, f0.w),
                                                          packlo(f1.x, f1.y), packlo(f1.z, f1.w));
            }
        }
        __syncthreads();
        gemm_tile(sb, SM_QH, SM_QL, SM_MH, SM_ML, T0, lane, acc);
    }

    // S -> St[m][t] (stride 132)
    {
        int tr = T0 + (lane >> 2);
        int mc = (lane & 3) * 2;
        #pragma unroll
        for (int nt = 0; nt < 8; nt++) {
            int m = nt * 8 + mc;
            St[m * 132 + tr] = acc[nt][0];
            St[(m + 1) * 132 + tr] = acc[nt][1];
            St[m * 132 + tr + 8] = acc[nt][2];
            St[(m + 1) * 132 + tr + 8] = acc[nt][3];
        }
    }
    __syncthreads();

    // ========== column path: S^T scratch + colmax ==========
    {
        int m = tid & 63, q = tid >> 6;
        float* pm = (float*)(smc + SM_PMAX);
        float mx = -3.4e38f;
        #pragma unroll
        for (int g = 0; g < 8; g++) {
            float4 v = *(float4*)&St[m * 132 + q * 32 + 4 * g];
            mx = fmaxf(mx, fmaxf(fmaxf(v.x, v.y), fmaxf(v.z, v.w)));
            *(float4*)&g_ST[(size_t)m * N + n0 + q * 32 + 4 * g] = v;
        }
        pm[q * 64 + m] = mx;
    }

    // ========== row path: softmax/shrink/L1 in regs ==========
    float a[MM];
    if (tid < TOK) {
        float mx = -3.4e38f;
        #pragma unroll
        for (int m = 0; m < MM; m++) { a[m] = St[m * 132 + tid]; mx = fmaxf(mx, a[m]); }
        float z = 0.f;
        #pragma unroll
        for (int m = 0; m < MM; m++) { a[m] = __expf(a[m] - mx); z += a[m]; }
        float invz = 1.0f / z, l1 = 0.f;
        #pragma unroll
        for (int m = 0; m < MM; m++) {
            float v = a[m] * invz, s2 = v - SHRINK_C;
            a[m] = (s2 > 0.f) ? s2 * v / (s2 + EPSV) : 0.f;
            l1 += a[m];
        }
        float sc = 1.0f / fmaxf(l1, EPSV);
        #pragma unroll
        for (int m = 0; m < MM; m++) a[m] *= sc;
    }
    __syncthreads();
    if (tid < MM) {
        float* pm = (float*)(smc + SM_PMAX);
        float mx = fmaxf(fmaxf(pm[tid], pm[64 + tid]), fmaxf(pm[128 + tid], pm[192 + tid]));
        atomicMax(&g_colmax[tid], encf(mx));
    }

    // ========== attn: fp32 restage + bf16 A-tiles (aliased into QH/QL) ==========
    if (tid < TOK) {
        #pragma unroll
        for (int m = 0; m < MM; m++) St[m * 132 + tid] = a[m];
        uint32_t rowb = (uint32_t)tid * 128u;
        #pragma unroll
        for (int g = 0; g < 8; g++) {
            float e0 = a[8 * g], e1 = a[8 * g + 1], e2 = a[8 * g + 2], e3 = a[8 * g + 3];
            float e4 = a[8 * g + 4], e5 = a[8 * g + 5], e6 = a[8 * g + 6], e7 = a[8 * g + 7];
            uint32_t off = swz(rowb + 16u * g);
            *(uint4*)(smc + SM_QH + off) = make_uint4(prmt_hi(e0, e1), prmt_hi(e2, e3),
                                                      prmt_hi(e4, e5), prmt_hi(e6, e7));
            *(uint4*)(smc + SM_QL + off) = make_uint4(packlo(e0, e1), packlo(e2, e3),
                                                      packlo(e4, e5), packlo(e6, e7));
        }
    }
    __syncthreads();
    #pragma unroll
    for (int r = 0; r < 8; r++) {
        int flat = tid + 256 * r;
        int n = flat >> 4, mg = flat & 15;
        *(float4*)&outA[(size_t)(n0 + n) * MM + 4 * mg] =
            make_float4(St[(4 * mg + 0) * 132 + n], St[(4 * mg + 1) * 132 + n],
                        St[(4 * mg + 2) * 132 + n], St[(4 * mg + 3) * 132 + n]);
    }
    __syncthreads();

    // ========== GEMM2: add_memory = attn @ mem, 8 d-chunks of 64 ==========
    const int tr = T0 + (lane >> 2);
    const int mc = (lane & 3) * 2;
    for (int cc = 0; cc < 8; cc++) {
        int d0 = cc * 64;
        {   // load mem[64 m][64 d] -> St stride 68
            #pragma unroll
            for (int g = 0; g < 4; g++) {
                int idx = tid + 256 * g;
                int m = idx >> 4, dq = idx & 15;
                *(float4*)&St[m * 68 + dq * 4] =
                    *(const float4*)(memg + (size_t)m * DD + d0 + dq * 4);
            }
        }
        __syncthreads();
        if (tid < 128) {   // transpose+convert -> memT[d][m] hi/lo (aliased MH/ML)
            int dl = tid & 63, mh = (tid >> 6) * 32;
            float v[32];
            #pragma unroll
            for (int j = 0; j < 32; j++) v[j] = St[(mh + j) * 68 + dl];
            uint32_t rowb = (uint32_t)dl * 128u + (uint32_t)mh * 2u;
            #pragma unroll
            for (int g = 0; g < 4; g++) {
                float e0 = v[8 * g], e1 = v[8 * g + 1], e2 = v[8 * g + 2], e3 = v[8 * g + 3];
                float e4 = v[8 * g + 4], e5 = v[8 * g + 5], e6 = v[8 * g + 6], e7 = v[8 * g + 7];
                uint32_t off = swz(rowb + 16u * g);
                *(uint4*)(smc + SM_MH + off) = make_uint4(prmt_hi(e0, e1), prmt_hi(e2, e3),
                                                          prmt_hi(e4, e5), prmt_hi(e6, e7));
                *(uint4*)(smc + SM_ML + off) = make_uint4(packlo(e0, e1), packlo(e2, e3),
                                                          packlo(e4, e5), packlo(e6, e7));
            }
        }
        __syncthreads();
        float acc2[8][4];
        #pragma unroll
        for (int i = 0; i < 8; i++)
            #pragma unroll
            for (int j = 0; j < 4; j++) acc2[i][j] = 0.f;
        gemm_tile(sb, SM_QH, SM_QL, SM_MH, SM_ML, T0, lane, acc2);
        // direct stores: lane pairs are contiguous (full 32B sectors per 4 lanes)
        {
            float* ob  = outO + (size_t)(n0 + tr) * (2 * DD) + DD + d0 + mc;
            float* ob8 = ob + (size_t)8 * (2 * DD);
            #pragma unroll
            for (int nt = 0; nt < 8; nt++) {
                *(float2*)(ob  + nt * 8) = make_float2(acc2[nt][0], acc2[nt][1]);
                *(float2*)(ob8 + nt * 8) = make_float2(acc2[nt][2], acc2[nt][3]);
            }
        }
        __syncthreads();
    }

    // ========== q copy -> out[:, 0:512] ==========
    {
        const float4* q4 = (const float4*)qg;
        float4* o4 = (float4*)outO;
        for (int idx = tid; idx < TOK * (DD / 4); idx += 256) {
            int t = idx >> 7, dq = idx & 127;
            o4[(size_t)(n0 + t) * (2 * DD / 4) + dq] = q4[(size_t)(n0 + t) * (DD / 4) + dq];
        }
    }
}

__global__ __launch_bounds__(256) void k2_colz(int N) {
    int m = blockIdx.y, s = blockIdx.x;
    float cmax = decf(g_colmax[m]);
    const float* row = g_ST + (size_t)m * N;
    float loc = 0.f;
    for (int i = threadIdx.x; i < 8192; i += 256) {
        int n = s * 8192 + i;
        if (n < N) loc += __expf(row[n] - cmax);
    }
    __shared__ float red[256];
    red[threadIdx.x] = loc; __syncthreads();
    for (int st = 128; st > 0; st >>= 1) {
        if (threadIdx.x < st) red[threadIdx.x] += red[threadIdx.x + st];
        __syncthreads();
    }
    if (threadIdx.x == 0) g_pZ[m * NS_MAX + s] = red[0];
}

__global__ __launch_bounds__(512) void k3_sparse(const float* __restrict__ qg, int N, int NS) {
    int m = blockIdx.y, s = blockIdx.x, tid = threadIdx.x;
    float cmax = decf(g_colmax[m]);
    float Z = 0.f;
    for (int j = 0; j < NS; j++) Z += g_pZ[m * NS_MAX + j];
    float invZ = 1.0f / Z;
    const float* row = g_ST + (size_t)m * N;
    __shared__ float ash_sh[512];
    float accv = 0.f, l1 = 0.f;
    for (int c = 0; c < 16; c++) {
        int n = s * 8192 + c * 512 + tid;
        float ash = 0.f;
        if (n < N) {
            float a = __expf(row[n] - cmax) * invZ;
            float s2 = a - SHRINK_C;
            if (s2 > 0.f) ash = s2 * a / (s2 + EPSV);
        }
        ash_sh[tid] = ash;
        l1 += ash;
        int any = __syncthreads_or(ash > 0.f);
        if (any) {
            int nb = s * 8192 + c * 512;
            for (int i = 0; i < 512; i++) {
                float w = ash_sh[i];
                if (w > 0.f) accv += w * qg[(size_t)(nb + i) * DD + tid];
            }
        }
        __syncthreads();
    }
    g_pvec[(size_t)(m * NS_MAX + s) * DD + tid] = accv;
    __shared__ float red[512];
    red[tid] = l1; __syncthreads();
    for (int st = 256; st > 0; st >>= 1) {
        if (tid < st) red[tid] += red[tid + st];
        __syncthreads();
    }
    if (tid == 0) g_pL1[m * NS_MAX + s] = red[0];
}

__global__ __launch_bounds__(512) void k4_gate(
    const float* __restrict__ memg,
    const float* __restrict__ Uw, const float* __restrict__ Ub,
    const float* __restrict__ Ww, const float* __restrict__ Wb,
    float* __restrict__ outM, int NS)
{
    int m = blockIdx.x, d = threadIdx.x;
    __shared__ float am[DD], ms[DD];
    float v = 0.f, l1 = 0.f;
    for (int j = 0; j < NS; j++) {
        v += g_pvec[(size_t)(m * NS_MAX + j) * DD + d];
        l1 += g_pL1[m * NS_MAX + j];
    }
    am[d] = v / fmaxf(l1, EPSV);
    ms[d] = memg[m * DD + d];
    __syncthreads();
    float acc = Ub[d] + Wb[d];
    const float4* uw4 = (const float4*)(Uw + (size_t)d * DD);
    const float4* ww4 = (const float4*)(Ww + (size_t)d * DD);
    const float4* am4 = (const float4*)am;
    const float4* ms4 = (const float4*)ms;
    #pragma unroll 4
    for (int k = 0; k < DD / 4; k++) {
        float4 u = uw4[k], w = ww4[k], aa = am4[k], s = ms4[k];
        acc += s.x * u.x + s.y * u.y + s.z * u.z + s.w * u.w;
        acc += aa.x * w.x + aa.y * w.y + aa.z * w.z + aa.w * w.w;
    }
    float g = 1.0f / (1.0f + __expf(-acc));
    outM[m * DD + d] = (1.0f - g) * ms[d] + g * am[d];
}

extern "C" void kernel_launch(void* const* d_in, const int* in_sizes, int n_in,
                              void* d_out, int out_size)
{
    const float* qg   = (const float*)d_in[0];
    const float* memg = (const float*)d_in[1];
    const float* Uw   = (const float*)d_in[2];
    const float* Ub   = (const float*)d_in[3];
    const float* Ww   = (const float*)d_in[4];
    const float* Wb   = (const float*)d_in[5];

    int N  = in_sizes[0] / DD;
    int NS = (N + 8191) / 8192;

    float* outO = (float*)d_out;
    float* outA = outO + (size_t)N * 2 * DD;
    float* outM = outA + (size_t)N * MM;

    cudaFuncSetAttribute((const void*)k1_main,
                         cudaFuncAttributeMaxDynamicSharedMemorySize, SMEM_TOTAL);

    k0_init<<<1, 64>>>();
    k1_main<<<N / TOK, 256, SMEM_TOTAL>>>(qg, memg, outO, outA, N);
    k2_colz<<<dim3(NS, MM), 256>>>(N);
    k3_sparse<<<dim3(NS, MM), 512>>>(qg, N, NS);
    k4_gate<<<MM, 512>>>(memg, Uw, Ub, Ww, Wb, outM, NS);
}

// round 8
// speedup vs baseline: 1.6761x; 1.1079x over previous
#include <cuda_runtime.h>
#include <cuda_fp16.h>
#include <cstdint>

#define DD 512
#define MM 64
#define TOK 128
#define SHRINK_C 0.0025f
#define EPSV 1e-12f
#define NS_MAX 16
#define NBCAP 512

__device__ float    g_ST[(size_t)MM * 65536];            // e^s, [M][N]
__device__ float    g_pZb[MM * NBCAP];                   // per-block column Z partials
__device__ float    g_pL1[MM * NS_MAX];
__device__ float    g_pvec[(size_t)MM * NS_MAX * DD];
__device__ uint32_t g_memk_h[8 * 2048];                  // GEMM1 B hi, swizzled images
__device__ uint32_t g_memk_l[8 * 2048];                  // GEMM1 B lo
__device__ uint32_t g_memt[8 * 2048];                    // GEMM2 B (memT), single fp16

// smem layout (bytes)
#define SM_PZ   0
#define SM_QH   1024
#define SM_QL   17408
#define SM_MH   33792
#define SM_ML   41984
#define SM_ST   50176
#define SMEM_TOTAL 83968
// AT (attn fp16) aliases SM_QH; GEMM2 B tile aliases SM_MH.

__device__ __forceinline__ uint32_t s2u(const void* p) {
    uint32_t a;
    asm("{ .reg .u64 t; cvta.to.shared.u64 t, %1; cvt.u32.u64 %0, t; }" : "=r"(a) : "l"(p));
    return a;
}
__device__ __forceinline__ uint32_t swz(uint32_t b) { return b ^ ((b >> 3) & 0x70u); }
__device__ __forceinline__ uint32_t f2h2(float a, float b) {
    __half2 h = __floats2half2_rn(a, b);
    return *reinterpret_cast<uint32_t*>(&h);
}
__device__ __forceinline__ uint32_t f2h2lo(float a, float b, uint32_t hi) {
    __half2 h = *reinterpret_cast<__half2*>(&hi);
    float2 f = __half22float2(h);
    __half2 l = __floats2half2_rn(a - f.x, b - f.y);
    return *reinterpret_cast<uint32_t*>(&l);
}
__device__ __forceinline__ void ldsm4(uint32_t* r, uint32_t addr) {
    asm volatile("ldmatrix.sync.aligned.m8n8.x4.shared.b16 {%0,%1,%2,%3}, [%4];"
        : "=r"(r[0]), "=r"(r[1]), "=r"(r[2]), "=r"(r[3]) : "r"(addr));
}
__device__ __forceinline__ void mma16816(float* d, const uint32_t* a, const uint32_t* b) {
    asm volatile("mma.sync.aligned.m16n8k16.row.col.f32.f16.f16.f32 "
        "{%0,%1,%2,%3}, {%4,%5,%6,%7}, {%8,%9}, {%0,%1,%2,%3};"
        : "+f"(d[0]), "+f"(d[1]), "+f"(d[2]), "+f"(d[3])
        : "r"(a[0]), "r"(a[1]), "r"(a[2]), "r"(a[3]), "r"(b[0]), "r"(b[1]));
}

// 3-term split GEMM tile: 16 tok x 64 cols x 64 k
__device__ __forceinline__ void gemm_tile3(uint32_t sb, uint32_t AH, uint32_t AL,
        uint32_t BH, uint32_t BL, int T0, int lane, float (*acc)[4])
{
    const int tile = lane >> 3, r = lane & 7;
    const uint32_t a_base = (uint32_t)(T0 + ((tile & 1) << 3) + r) * 128u + (uint32_t)((tile >> 1) << 4);
    const uint32_t b_rr = (uint32_t)(((tile >> 1) << 3) + r);
    const uint32_t b_kb0 = (uint32_t)((tile & 1) << 4);
    #pragma unroll
    for (int s = 0; s < 4; s++) {
        uint32_t ah[4], al[4];
        uint32_t aoff = swz(a_base + (uint32_t)s * 32u);
        ldsm4(ah, sb + AH + aoff);
        ldsm4(al, sb + AL + aoff);
        #pragma unroll
        for (int g = 0; g < 4; g++) {
            uint32_t bh[4], bl[4];
            uint32_t boff = swz(((uint32_t)g * 16u + b_rr) * 128u + (uint32_t)s * 32u + b_kb0);
            ldsm4(bh, sb + BH + boff);
            ldsm4(bl, sb + BL + boff);
            mma16816(acc[2 * g],     ah, bh);
            mma16816(acc[2 * g + 1], ah, bh + 2);
            mma16816(acc[2 * g],     ah, bl);
            mma16816(acc[2 * g + 1], ah, bl + 2);
            mma16816(acc[2 * g],     al, bh);
            mma16816(acc[2 * g + 1], al, bh + 2);
        }
    }
}

// single-term GEMM tile (no-cancellation path)
__device__ __forceinline__ void gemm_tile1(uint32_t sb, uint32_t A, uint32_t B,
        int T0, int lane, float (*acc)[4])
{
    const int tile = lane >> 3, r = lane & 7;
    const uint32_t a_base = (uint32_t)(T0 + ((tile & 1) << 3) + r) * 128u + (uint32_t)((tile >> 1) << 4);
    const uint32_t b_rr = (uint32_t)(((tile >> 1) << 3) + r);
    const uint32_t b_kb0 = (uint32_t)((tile & 1) << 4);
    #pragma unroll
    for (int s = 0; s < 4; s++) {
        uint32_t a[4];
        ldsm4(a, sb + A + swz(a_base + (uint32_t)s * 32u));
        #pragma unroll
        for (int g = 0; g < 4; g++) {
            uint32_t b[4];
            ldsm4(b, sb + B + swz(((uint32_t)g * 16u + b_rr) * 128u + (uint32_t)s * 32u + b_kb0));
            mma16816(acc[2 * g],     a, b);
            mma16816(acc[2 * g + 1], a, b + 2);
        }
    }
}

// ---------------- k0b: precompute mem fp16 tile images ----------------
__global__ __launch_bounds__(256) void k0_prep(const float* __restrict__ memg) {
    int idx = blockIdx.x * 256 + threadIdx.x;
    if (idx < 16384) {       // k-major hi/lo: chunk c, row m, k-pair p
        int c = idx >> 11, rem = idx & 2047, m = rem >> 5, p = rem & 31;
        int k0 = c * 64 + 2 * p;
        float a = memg[m * DD + k0], b = memg[m * DD + k0 + 1];
        uint32_t h = f2h2(a, b);
        uint32_t l = f2h2lo(a, b, h);
        uint32_t off = ((uint32_t)c * 8192u + swz((uint32_t)m * 128u + (uint32_t)p * 4u)) >> 2;
        g_memk_h[off] = h;
        g_memk_l[off] = l;
    } else {                 // d-major single: chunk cc, row dl, m-pair mp
        int j = idx - 16384;
        int cc = j >> 11, rem = j & 2047, dl = rem >> 5, mp = rem & 31;
        int d = cc * 64 + dl;
        float a = memg[(2 * mp) * DD + d], b = memg[(2 * mp + 1) * DD + d];
        uint32_t off = ((uint32_t)cc * 8192u + swz((uint32_t)dl * 128u + (uint32_t)mp * 4u)) >> 2;
        g_memt[off] = f2h2(a, b);
    }
}

// ---------------- k1: main kernel ----------------
__global__ __launch_bounds__(256, 2) void k1_main(
    const float* __restrict__ qg,
    float* __restrict__ outO, float* __restrict__ outA, int N)
{
    extern __shared__ char smc[];
    const uint32_t sb = s2u(smc);
    const int tid = threadIdx.x, wid = tid >> 5, lane = tid & 31;
    const int n0 = blockIdx.x * TOK;
    const int T0 = wid * 16;
    float* St = (float*)(smc + SM_ST);
    float* pm = (float*)(smc + SM_PZ);

    // ========== GEMM1: S[128 tok][64 m], 8 k-chunks of 64, fp16 3-term ==========
    float acc[8][4];
    #pragma unroll
    for (int i = 0; i < 8; i++)
        #pragma unroll
        for (int j = 0; j < 4; j++) acc[i][j] = 0.f;

    for (int c = 0; c < 8; c++) {
        if (c > 0) __syncthreads();
        // B tiles: straight copies of precomputed swizzled images (issue LDGs first)
        const uint4* kh = (const uint4*)(g_memk_h + c * 2048);
        const uint4* kl = (const uint4*)(g_memk_l + c * 2048);
        uint4 b0 = kh[tid], b1 = kh[tid + 256], b2 = kl[tid], b3 = kl[tid + 256];
        // q chunk -> fp16 hi/lo
        {
            int t = tid >> 1, h = tid & 1;
            const float4* src = (const float4*)(qg + (size_t)(n0 + t) * DD + c * 64 + h * 32);
            uint32_t rowb = (uint32_t)t * 128u + (uint32_t)h * 64u;
            #pragma unroll
            for (int g = 0; g < 4; g++) {
                float4 f0 = src[2 * g], f1 = src[2 * g + 1];
                uint32_t h0 = f2h2(f0.x, f0.y), h1 = f2h2(f0.z, f0.w);
                uint32_t h2 = f2h2(f1.x, f1.y), h3 = f2h2(f1.z, f1.w);
                uint32_t off = swz(rowb + 16u * g);
                *(uint4*)(smc + SM_QH + off) = make_uint4(h0, h1, h2, h3);
                *(uint4*)(smc + SM_QL + off) = make_uint4(
                    f2h2lo(f0.x, f0.y, h0), f2h2lo(f0.z, f0.w, h1),
                    f2h2lo(f1.x, f1.y, h2), f2h2lo(f1.z, f1.w, h3));
            }
        }
        *(uint4*)(smc + SM_MH + tid * 16)        = b0;
        *(uint4*)(smc + SM_MH + tid * 16 + 4096) = b1;
        *(uint4*)(smc + SM_ML + tid * 16)        = b2;
        *(uint4*)(smc + SM_ML + tid * 16 + 4096) = b3;
        __syncthreads();
        gemm_tile3(sb, SM_QH, SM_QL, SM_MH, SM_ML, T0, lane, acc);
    }

    // scatter S -> St[m][t] (stride 132)
    {
        int tr = T0 + (lane >> 2);
        int mc = (lane & 3) * 2;
        #pragma unroll
        for (int nt = 0; nt < 8; nt++) {
            int m = nt * 8 + mc;
            St[m * 132 + tr] = acc[nt][0];
            St[(m + 1) * 132 + tr] = acc[nt][1];
            St[m * 132 + tr + 8] = acc[nt][2];
            St[(m + 1) * 132 + tr + 8] = acc[nt][3];
        }
    }
    __syncthreads();

    // ========== row path: softmax/shrink/L1; write e^s back into St ==========
    float a[MM];
    if (tid < TOK) {
        float mx = -3.4e38f;
        #pragma unroll
        for (int m = 0; m < MM; m++) { a[m] = St[m * 132 + tid]; mx = fmaxf(mx, a[m]); }
        float z = 0.f;
        #pragma unroll
        for (int m = 0; m < MM; m++) { a[m] = __expf(a[m] - mx); z += a[m]; }
        float emx = __expf(mx);
        #pragma unroll
        for (int m = 0; m < MM; m++) St[m * 132 + tid] = a[m] * emx;   // e^s
        float invz = 1.0f / z, l1 = 0.f;
        #pragma unroll
        for (int m = 0; m < MM; m++) {
            float v = a[m] * invz, s2 = v - SHRINK_C;
            a[m] = (s2 > 0.f) ? s2 * v / (s2 + EPSV) : 0.f;
            l1 += a[m];
        }
        float sc = 1.0f / fmaxf(l1, EPSV);
        #pragma unroll
        for (int m = 0; m < MM; m++) a[m] *= sc;
    }
    __syncthreads();

    // ========== column pass: write e^s scratch + per-block Z partials ==========
    {
        int m = tid & 63, q = tid >> 6;
        float zp = 0.f;
        #pragma unroll
        for (int g = 0; g < 8; g++) {
            float4 v = *(float4*)&St[m * 132 + q * 32 + 4 * g];
            zp += (v.x + v.y) + (v.z + v.w);
            *(float4*)&g_ST[(size_t)m * N + n0 + q * 32 + 4 * g] = v;
        }
        pm[q * 64 + m] = zp;
    }
    __syncthreads();
    if (tid < MM)
        g_pZb[tid * NBCAP + blockIdx.x] =
            (pm[tid] + pm[64 + tid]) + (pm[128 + tid] + pm[192 + tid]);

    // ========== attn: fp32 restage + fp16 A tile (aliases QH) ==========
    if (tid < TOK) {
        #pragma unroll
        for (int m = 0; m < MM; m++) St[m * 132 + tid] = a[m];
        uint32_t rowb = (uint32_t)tid * 128u;
        #pragma unroll
        for (int g = 0; g < 8; g++) {
            uint32_t off = swz(rowb + 16u * g);
            *(uint4*)(smc + SM_QH + off) = make_uint4(
                f2h2(a[8 * g], a[8 * g + 1]), f2h2(a[8 * g + 2], a[8 * g + 3]),
                f2h2(a[8 * g + 4], a[8 * g + 5]), f2h2(a[8 * g + 6], a[8 * g + 7]));
        }
    }
    __syncthreads();
    #pragma unroll
    for (int r = 0; r < 8; r++) {
        int flat = tid + 256 * r;
        int n = flat >> 4, mg = flat & 15;
        *(float4*)&outA[(size_t)(n0 + n) * MM + 4 * mg] =
            make_float4(St[(4 * mg + 0) * 132 + n], St[(4 * mg + 1) * 132 + n],
                        St[(4 * mg + 2) * 132 + n], St[(4 * mg + 3) * 132 + n]);
    }
    __syncthreads();

    // ========== GEMM2: add_memory = attn @ mem, single-term fp16, 8 d-chunks ==========
    const int tr = T0 + (lane >> 2);
    const int mc = (lane & 3) * 2;
    for (int cc = 0; cc < 8; cc++) {
        const uint4* mt = (const uint4*)(g_memt + cc * 2048);
        uint4 b0 = mt[tid], b1 = mt[tid + 256];
        *(uint4*)(smc + SM_MH + tid * 16)        = b0;
        *(uint4*)(smc + SM_MH + tid * 16 + 4096) = b1;
        __syncthreads();
        float acc2[8][4];
        #pragma unroll
        for (int i = 0; i < 8; i++)
            #pragma unroll
            for (int j = 0; j < 4; j++) acc2[i][j] = 0.f;
        gemm_tile1(sb, SM_QH, SM_MH, T0, lane, acc2);
        {
            float* ob  = outO + (size_t)(n0 + tr) * (2 * DD) + DD + cc * 64 + mc;
            float* ob8 = ob + (size_t)8 * (2 * DD);
            #pragma unroll
            for (int nt = 0; nt < 8; nt++) {
                *(float2*)(ob  + nt * 8) = make_float2(acc2[nt][0], acc2[nt][1]);
                *(float2*)(ob8 + nt * 8) = make_float2(acc2[nt][2], acc2[nt][3]);
            }
        }
        __syncthreads();
    }

    // ========== q copy -> out[:, 0:512] ==========
    {
        const float4* q4 = (const float4*)qg;
        float4* o4 = (float4*)outO;
        for (int idx = tid; idx < TOK * (DD / 4); idx += 256) {
            int t = idx >> 7, dq = idx & 127;
            o4[(size_t)(n0 + t) * (2 * DD / 4) + dq] = q4[(size_t)(n0 + t) * (DD / 4) + dq];
        }
    }
}

// ---------------- k3: shrink + sparse vec/L1 partials (reads e^s) ----------------
__global__ __launch_bounds__(512) void k3_sparse(const float* __restrict__ qg, int N, int NS, int NB) {
    int m = blockIdx.y, s = blockIdx.x, tid = threadIdx.x;
    __shared__ float red[512];
    float zl = 0.f;
    for (int i = tid; i < NB; i += 512) zl += g_pZb[m * NBCAP + i];
    red[tid] = zl; __syncthreads();
    for (int st = 256; st > 0; st >>= 1) {
        if (tid < st) red[tid] += red[tid + st];
        __syncthreads();
    }
    float invZ = 1.0f / red[0];
    __syncthreads();

    const float* row = g_ST + (size_t)m * N;
    __shared__ float ash_sh[512];
    float accv = 0.f, l1 = 0.f;
    for (int c = 0; c < 16; c++) {
        int n = s * 8192 + c * 512 + tid;
        float ash = 0.f;
        if (n < N) {
            float a = row[n] * invZ;
            float s2 = a - SHRINK_C;
            if (s2 > 0.f) ash = s2 * a / (s2 + EPSV);
        }
        ash_sh[tid] = ash;
        l1 += ash;
        int any = __syncthreads_or(ash > 0.f);
        if (any) {
            int nb = s * 8192 + c * 512;
            for (int i = 0; i < 512; i++) {
                float w = ash_sh[i];
                if (w > 0.f) accv += w * qg[(size_t)(nb + i) * DD + tid];
            }
        }
        __syncthreads();
    }
    g_pvec[(size_t)(m * NS_MAX + s) * DD + tid] = accv;
    red[tid] = l1; __syncthreads();
    for (int st = 256; st > 0; st >>= 1) {
        if (tid < st) red[tid] += red[tid + st];
        __syncthreads();
    }
    if (tid == 0) g_pL1[m * NS_MAX + s] = red[0];
}

// ---------------- k4: add_mem, gate, new_mem ----------------
__global__ __launch_bounds__(512) void k4_gate(
    const float* __restrict__ memg,
    const float* __restrict__ Uw, const float* __restrict__ Ub,
    const float* __restrict__ Ww, const float* __restrict__ Wb,
    float* __restrict__ outM, int NS)
{
    int m = blockIdx.x, d = threadIdx.x;
    __shared__ float am[DD], ms[DD];
    float v = 0.f, l1 = 0.f;
    for (int j = 0; j < NS; j++) {
        v += g_pvec[(size_t)(m * NS_MAX + j) * DD + d];
        l1 += g_pL1[m * NS_MAX + j];
    }
    am[d] = v / fmaxf(l1, EPSV);
    ms[d] = memg[m * DD + d];
    __syncthreads();
    float acc = Ub[d] + Wb[d];
    const float4* uw4 = (const float4*)(Uw + (size_t)d * DD);
    const float4* ww4 = (const float4*)(Ww + (size_t)d * DD);
    const float4* am4 = (const float4*)am;
    const float4* ms4 = (const float4*)ms;
    #pragma unroll 4
    for (int k = 0; k < DD / 4; k++) {
        float4 u = uw4[k], w = ww4[k], aa = am4[k], s = ms4[k];
        acc += s.x * u.x + s.y * u.y + s.z * u.z + s.w * u.w;
        acc += aa.x * w.x + aa.y * w.y + aa.z * w.z + aa.w * w.w;
    }
    float g = 1.0f / (1.0f + __expf(-acc));
    outM[m * DD + d] = (1.0f - g) * ms[d] + g * am[d];
}

extern "C" void kernel_launch(void* const* d_in, const int* in_sizes, int n_in,
                              void* d_out, int out_size)
{
    const float* qg   = (const float*)d_in[0];
    const float* memg = (const float*)d_in[1];
    const float* Uw   = (const float*)d_in[2];
    const float* Ub   = (const float*)d_in[3];
    const float* Ww   = (const float*)d_in[4];
    const float* Wb   = (const float*)d_in[5];

    int N  = in_sizes[0] / DD;
    int NS = (N + 8191) / 8192;
    int NB = N / TOK;

    float* outO = (float*)d_out;
    float* outA = outO + (size_t)N * 2 * DD;
    float* outM = outA + (size_t)N * MM;

    cudaFuncSetAttribute((const void*)k1_main,
                         cudaFuncAttributeMaxDynamicSharedMemorySize, SMEM_TOTAL);

    k0_prep<<<128, 256>>>(memg);
    k1_main<<<NB, 256, SMEM_TOTAL>>>(qg, outO, outA, N);
    k3_sparse<<<dim3(NS, MM), 512>>>(qg, N, NS, NB);
    k4_gate<<<MM, 512>>>(memg, Uw, Ub, Ww, Wb, outM, NS);
}

// round 9
// speedup vs baseline: 1.9072x; 1.1379x over previous
#include <cuda_runtime.h>
#include <cuda_fp16.h>
#include <cstdint>

#define DD 512
#define MM 64
#define TOK 128
#define SHRINK_C 0.0025f
#define EPSV 1e-12f
#define NS_MAX 16
#define NBCAP 512

__device__ float    g_ST[(size_t)MM * 65536];            // e^s, [M][N]
__device__ float    g_pZb[MM * NBCAP];                   // per-block column Z partials
__device__ float    g_pL1[MM * NS_MAX];
__device__ float    g_pvec[(size_t)MM * NS_MAX * DD];
__device__ float    g_am[MM * DD];                       // add_mem (normalized)
__device__ uint32_t g_memk_h[8 * 2048];                  // GEMM1 B hi, swizzled images
__device__ uint32_t g_memk_l[8 * 2048];                  // GEMM1 B lo
__device__ uint32_t g_memt[8 * 2048];                    // GEMM2 B (memT), single fp16

// smem layout (bytes)
#define SM_PZ   0
#define SM_QH   1024
#define SM_QL   17408
#define SM_MH   33792
#define SM_ML   41984
#define SM_ST   50176
#define SMEM_TOTAL 83968
// AT (attn fp16) aliases SM_QH; GEMM2 B tile aliases SM_MH.

__device__ __forceinline__ uint32_t s2u(const void* p) {
    uint32_t a;
    asm("{ .reg .u64 t; cvta.to.shared.u64 t, %1; cvt.u32.u64 %0, t; }" : "=r"(a) : "l"(p));
    return a;
}
__device__ __forceinline__ uint32_t swz(uint32_t b) { return b ^ ((b >> 3) & 0x70u); }
__device__ __forceinline__ uint32_t f2h2(float a, float b) {
    __half2 h = __floats2half2_rn(a, b);
    return *reinterpret_cast<uint32_t*>(&h);
}
__device__ __forceinline__ uint32_t f2h2lo(float a, float b, uint32_t hi) {
    __half2 h = *reinterpret_cast<__half2*>(&hi);
    float2 f = __half22float2(h);
    __half2 l = __floats2half2_rn(a - f.x, b - f.y);
    return *reinterpret_cast<uint32_t*>(&l);
}
__device__ __forceinline__ void ldsm4(uint32_t* r, uint32_t addr) {
    asm volatile("ldmatrix.sync.aligned.m8n8.x4.shared.b16 {%0,%1,%2,%3}, [%4];"
        : "=r"(r[0]), "=r"(r[1]), "=r"(r[2]), "=r"(r[3]) : "r"(addr));
}
__device__ __forceinline__ void mma16816(float* d, const uint32_t* a, const uint32_t* b) {
    asm volatile("mma.sync.aligned.m16n8k16.row.col.f32.f16.f16.f32 "
        "{%0,%1,%2,%3}, {%4,%5,%6,%7}, {%8,%9}, {%0,%1,%2,%3};"
        : "+f"(d[0]), "+f"(d[1]), "+f"(d[2]), "+f"(d[3])
        : "r"(a[0]), "r"(a[1]), "r"(a[2]), "r"(a[3]), "r"(b[0]), "r"(b[1]));
}

// 3-term split GEMM tile: 16 tok x 64 cols x 64 k
__device__ __forceinline__ void gemm_tile3(uint32_t sb, uint32_t AH, uint32_t AL,
        uint32_t BH, uint32_t BL, int T0, int lane, float (*acc)[4])
{
    const int tile = lane >> 3, r = lane & 7;
    const uint32_t a_base = (uint32_t)(T0 + ((tile & 1) << 3) + r) * 128u + (uint32_t)((tile >> 1) << 4);
    const uint32_t b_rr = (uint32_t)(((tile >> 1) << 3) + r);
    const uint32_t b_kb0 = (uint32_t)((tile & 1) << 4);
    #pragma unroll
    for (int s = 0; s < 4; s++) {
        uint32_t ah[4], al[4];
        uint32_t aoff = swz(a_base + (uint32_t)s * 32u);
        ldsm4(ah, sb + AH + aoff);
        ldsm4(al, sb + AL + aoff);
        #pragma unroll
        for (int g = 0; g < 4; g++) {
            uint32_t bh[4], bl[4];
            uint32_t boff = swz(((uint32_t)g * 16u + b_rr) * 128u + (uint32_t)s * 32u + b_kb0);
            ldsm4(bh, sb + BH + boff);
            ldsm4(bl, sb + BL + boff);
            mma16816(acc[2 * g],     ah, bh);
            mma16816(acc[2 * g + 1], ah, bh + 2);
            mma16816(acc[2 * g],     ah, bl);
            mma16816(acc[2 * g + 1], ah, bl + 2);
            mma16816(acc[2 * g],     al, bh);
            mma16816(acc[2 * g + 1], al, bh + 2);
        }
    }
}

// single-term GEMM tile (no-cancellation path)
__device__ __forceinline__ void gemm_tile1(uint32_t sb, uint32_t A, uint32_t B,
        int T0, int lane, float (*acc)[4])
{
    const int tile = lane >> 3, r = lane & 7;
    const uint32_t a_base = (uint32_t)(T0 + ((tile & 1) << 3) + r) * 128u + (uint32_t)((tile >> 1) << 4);
    const uint32_t b_rr = (uint32_t)(((tile >> 1) << 3) + r);
    const uint32_t b_kb0 = (uint32_t)((tile & 1) << 4);
    #pragma unroll
    for (int s = 0; s < 4; s++) {
        uint32_t a[4];
        ldsm4(a, sb + A + swz(a_base + (uint32_t)s * 32u));
        #pragma unroll
        for (int g = 0; g < 4; g++) {
            uint32_t b[4];
            ldsm4(b, sb + B + swz(((uint32_t)g * 16u + b_rr) * 128u + (uint32_t)s * 32u + b_kb0));
            mma16816(acc[2 * g],     a, b);
            mma16816(acc[2 * g + 1], a, b + 2);
        }
    }
}

// ---------------- k0b: precompute mem fp16 tile images ----------------
__global__ __launch_bounds__(256) void k0_prep(const float* __restrict__ memg) {
    int idx = blockIdx.x * 256 + threadIdx.x;
    if (idx < 16384) {       // k-major hi/lo: chunk c, row m, k-pair p
        int c = idx >> 11, rem = idx & 2047, m = rem >> 5, p = rem & 31;
        int k0 = c * 64 + 2 * p;
        float a = memg[m * DD + k0], b = memg[m * DD + k0 + 1];
        uint32_t h = f2h2(a, b);
        uint32_t l = f2h2lo(a, b, h);
        uint32_t off = ((uint32_t)c * 8192u + swz((uint32_t)m * 128u + (uint32_t)p * 4u)) >> 2;
        g_memk_h[off] = h;
        g_memk_l[off] = l;
    } else {                 // d-major single: chunk cc, row dl, m-pair mp
        int j = idx - 16384;
        int cc = j >> 11, rem = j & 2047, dl = rem >> 5, mp = rem & 31;
        int d = cc * 64 + dl;
        float a = memg[(2 * mp) * DD + d], b = memg[(2 * mp + 1) * DD + d];
        uint32_t off = ((uint32_t)cc * 8192u + swz((uint32_t)dl * 128u + (uint32_t)mp * 4u)) >> 2;
        g_memt[off] = f2h2(a, b);
    }
}

// ---------------- k1: main kernel ----------------
__global__ __launch_bounds__(256, 2) void k1_main(
    const float* __restrict__ qg,
    float* __restrict__ outO, float* __restrict__ outA, int N)
{
    extern __shared__ char smc[];
    const uint32_t sb = s2u(smc);
    const int tid = threadIdx.x, wid = tid >> 5, lane = tid & 31;
    const int n0 = blockIdx.x * TOK;
    const int T0 = wid * 16;
    float* St = (float*)(smc + SM_ST);
    float* pm = (float*)(smc + SM_PZ);

    // ========== GEMM1: S[128 tok][64 m], 8 k-chunks of 64, fp16 3-term ==========
    float acc[8][4];
    #pragma unroll
    for (int i = 0; i < 8; i++)
        #pragma unroll
        for (int j = 0; j < 4; j++) acc[i][j] = 0.f;

    for (int c = 0; c < 8; c++) {
        if (c > 0) __syncthreads();
        // B tiles: straight copies of precomputed swizzled images (issue LDGs first)
        const uint4* kh = (const uint4*)(g_memk_h + c * 2048);
        const uint4* kl = (const uint4*)(g_memk_l + c * 2048);
        uint4 b0 = kh[tid], b1 = kh[tid + 256], b2 = kl[tid], b3 = kl[tid + 256];
        // q chunk -> fp16 hi/lo; fused q-copy to out[:, 0:512]
        {
            int t = tid >> 1, h = tid & 1;
            const float4* src = (const float4*)(qg + (size_t)(n0 + t) * DD + c * 64 + h * 32);
            float* oq = outO + (size_t)(n0 + t) * (2 * DD) + c * 64 + h * 32;
            uint32_t rowb = (uint32_t)t * 128u + (uint32_t)h * 64u;
            #pragma unroll
            for (int g = 0; g < 4; g++) {
                float4 f0 = src[2 * g], f1 = src[2 * g + 1];
                *(float4*)(oq + 8 * g)     = f0;
                *(float4*)(oq + 8 * g + 4) = f1;
                uint32_t h0 = f2h2(f0.x, f0.y), h1 = f2h2(f0.z, f0.w);
                uint32_t h2 = f2h2(f1.x, f1.y), h3 = f2h2(f1.z, f1.w);
                uint32_t off = swz(rowb + 16u * g);
                *(uint4*)(smc + SM_QH + off) = make_uint4(h0, h1, h2, h3);
                *(uint4*)(smc + SM_QL + off) = make_uint4(
                    f2h2lo(f0.x, f0.y, h0), f2h2lo(f0.z, f0.w, h1),
                    f2h2lo(f1.x, f1.y, h2), f2h2lo(f1.z, f1.w, h3));
            }
        }
        *(uint4*)(smc + SM_MH + tid * 16)        = b0;
        *(uint4*)(smc + SM_MH + tid * 16 + 4096) = b1;
        *(uint4*)(smc + SM_ML + tid * 16)        = b2;
        *(uint4*)(smc + SM_ML + tid * 16 + 4096) = b3;
        __syncthreads();
        gemm_tile3(sb, SM_QH, SM_QL, SM_MH, SM_ML, T0, lane, acc);
    }

    // scatter S -> St[m][t] (stride 132)
    {
        int tr = T0 + (lane >> 2);
        int mc = (lane & 3) * 2;
        #pragma unroll
        for (int nt = 0; nt < 8; nt++) {
            int m = nt * 8 + mc;
            St[m * 132 + tr] = acc[nt][0];
            St[(m + 1) * 132 + tr] = acc[nt][1];
            St[m * 132 + tr + 8] = acc[nt][2];
            St[(m + 1) * 132 + tr + 8] = acc[nt][3];
        }
    }
    __syncthreads();

    // ========== row path: softmax/shrink/L1; write e^s back into St ==========
    float a[MM];
    if (tid < TOK) {
        float mx = -3.4e38f;
        #pragma unroll
        for (int m = 0; m < MM; m++) { a[m] = St[m * 132 + tid]; mx = fmaxf(mx, a[m]); }
        float z = 0.f;
        #pragma unroll
        for (int m = 0; m < MM; m++) { a[m] = __expf(a[m] - mx); z += a[m]; }
        float emx = __expf(mx);
        #pragma unroll
        for (int m = 0; m < MM; m++) St[m * 132 + tid] = a[m] * emx;   // e^s
        float invz = 1.0f / z, l1 = 0.f;
        #pragma unroll
        for (int m = 0; m < MM; m++) {
            float v = a[m] * invz, s2 = v - SHRINK_C;
            a[m] = (s2 > 0.f) ? s2 * v / (s2 + EPSV) : 0.f;
            l1 += a[m];
        }
        float sc = 1.0f / fmaxf(l1, EPSV);
        #pragma unroll
        for (int m = 0; m < MM; m++) a[m] *= sc;
    }
    __syncthreads();

    // ========== column pass: write e^s scratch + per-block Z partials ==========
    {
        int m = tid & 63, q = tid >> 6;
        float zp = 0.f;
        #pragma unroll
        for (int g = 0; g < 8; g++) {
            float4 v = *(float4*)&St[m * 132 + q * 32 + 4 * g];
            zp += (v.x + v.y) + (v.z + v.w);
            *(float4*)&g_ST[(size_t)m * N + n0 + q * 32 + 4 * g] = v;
        }
        pm[q * 64 + m] = zp;
    }
    __syncthreads();
    if (tid < MM)
        g_pZb[tid * NBCAP + blockIdx.x] =
            (pm[tid] + pm[64 + tid]) + (pm[128 + tid] + pm[192 + tid]);

    // ========== attn: fp32 restage + fp16 A tile (aliases QH) ==========
    if (tid < TOK) {
        #pragma unroll
        for (int m = 0; m < MM; m++) St[m * 132 + tid] = a[m];
        uint32_t rowb = (uint32_t)tid * 128u;
        #pragma unroll
        for (int g = 0; g < 8; g++) {
            uint32_t off = swz(rowb + 16u * g);
            *(uint4*)(smc + SM_QH + off) = make_uint4(
                f2h2(a[8 * g], a[8 * g + 1]), f2h2(a[8 * g + 2], a[8 * g + 3]),
                f2h2(a[8 * g + 4], a[8 * g + 5]), f2h2(a[8 * g + 6], a[8 * g + 7]));
        }
    }
    __syncthreads();
    #pragma unroll
    for (int r = 0; r < 8; r++) {
        int flat = tid + 256 * r;
        int n = flat >> 4, mg = flat & 15;
        *(float4*)&outA[(size_t)(n0 + n) * MM + 4 * mg] =
            make_float4(St[(4 * mg + 0) * 132 + n], St[(4 * mg + 1) * 132 + n],
                        St[(4 * mg + 2) * 132 + n], St[(4 * mg + 3) * 132 + n]);
    }
    __syncthreads();

    // ========== GEMM2: add_memory = attn @ mem, single-term fp16, 8 d-chunks ==========
    const int tr = T0 + (lane >> 2);
    const int mc = (lane & 3) * 2;
    for (int cc = 0; cc < 8; cc++) {
        const uint4* mt = (const uint4*)(g_memt + cc * 2048);
        uint4 b0 = mt[tid], b1 = mt[tid + 256];
        *(uint4*)(smc + SM_MH + tid * 16)        = b0;
        *(uint4*)(smc + SM_MH + tid * 16 + 4096) = b1;
        __syncthreads();
        float acc2[8][4];
        #pragma unroll
        for (int i = 0; i < 8; i++)
            #pragma unroll
            for (int j = 0; j < 4; j++) acc2[i][j] = 0.f;
        gemm_tile1(sb, SM_QH, SM_MH, T0, lane, acc2);
        {
            float* ob  = outO + (size_t)(n0 + tr) * (2 * DD) + DD + cc * 64 + mc;
            float* ob8 = ob + (size_t)8 * (2 * DD);
            #pragma unroll
            for (int nt = 0; nt < 8; nt++) {
                *(float2*)(ob  + nt * 8) = make_float2(acc2[nt][0], acc2[nt][1]);
                *(float2*)(ob8 + nt * 8) = make_float2(acc2[nt][2], acc2[nt][3]);
            }
        }
        __syncthreads();
    }
}

// ---------------- k3: shrink + sparse vec/L1 partials (reads e^s) ----------------
__global__ __launch_bounds__(512) void k3_sparse(const float* __restrict__ qg, int N, int NS, int NB) {
    int m = blockIdx.y, s = blockIdx.x, tid = threadIdx.x;
    __shared__ float red[512];
    float zl = 0.f;
    for (int i = tid; i < NB; i += 512) zl += g_pZb[m * NBCAP + i];
    red[tid] = zl; __syncthreads();
    for (int st = 256; st > 0; st >>= 1) {
        if (tid < st) red[tid] += red[tid + st];
        __syncthreads();
    }
    float invZ = 1.0f / red[0];
    __syncthreads();

    const float* row = g_ST + (size_t)m * N;
    __shared__ float ash_sh[512];
    float accv = 0.f, l1 = 0.f;
    for (int c = 0; c < 16; c++) {
        int n = s * 8192 + c * 512 + tid;
        float ash = 0.f;
        if (n < N) {
            float a = row[n] * invZ;
            float s2 = a - SHRINK_C;
            if (s2 > 0.f) ash = s2 * a / (s2 + EPSV);
        }
        ash_sh[tid] = ash;
        l1 += ash;
        int any = __syncthreads_or(ash > 0.f);
        if (any) {
            int nb = s * 8192 + c * 512;
            for (int i = 0; i < 512; i++) {
                float w = ash_sh[i];
                if (w > 0.f) accv += w * qg[(size_t)(nb + i) * DD + tid];
            }
        }
        __syncthreads();
    }
    g_pvec[(size_t)(m * NS_MAX + s) * DD + tid] = accv;
    red[tid] = l1; __syncthreads();
    for (int st = 256; st > 0; st >>= 1) {
        if (tid < st) red[tid] += red[tid + st];
        __syncthreads();
    }
    if (tid == 0) g_pL1[m * NS_MAX + s] = red[0];
}

// ---------------- k4a: reduce partials -> am ----------------
__global__ __launch_bounds__(512) void k4a_am(int NS) {
    int m = blockIdx.x, d = threadIdx.x;
    float v = 0.f, l1 = 0.f;
    for (int j = 0; j < NS; j++) {
        v += g_pvec[(size_t)(m * NS_MAX + j) * DD + d];
        l1 += g_pL1[m * NS_MAX + j];
    }
    g_am[m * DD + d] = v / fmaxf(l1, EPSV);
}

// ---------------- k4b: gate GEMV + new_mem (4 m x 128 d per block) ----------------
__global__ __launch_bounds__(128) void k4b_gate(
    const float* __restrict__ memg,
    const float* __restrict__ Uw, const float* __restrict__ Ub,
    const float* __restrict__ Ww, const float* __restrict__ Wb,
    float* __restrict__ outM)
{
    const int tid = threadIdx.x;
    const int m0 = blockIdx.y * 4;
    const int d = blockIdx.x * 128 + tid;
    __shared__ float am_s[4][DD], ms_s[4][DD];

    for (int i = tid; i < 512; i += 128) {           // i over [4 m][128 float4]
        int mi = i >> 7, k4 = i & 127;
        ((float4*)am_s[mi])[k4] = ((const float4*)(g_am + (m0 + mi) * DD))[k4];
        ((float4*)ms_s[mi])[k4] = ((const float4*)(memg + (m0 + mi) * DD))[k4];
    }
    __syncthreads();

    float a0 = 0.f, a1 = 0.f, a2 = 0.f, a3 = 0.f;
    const float4* uw4 = (const float4*)(Uw + (size_t)d * DD);
    const float4* ww4 = (const float4*)(Ww + (size_t)d * DD);
    #pragma unroll 4
    for (int k = 0; k < DD / 4; k++) {
        float4 u = uw4[k], w = ww4[k];
        float4 s0 = ((float4*)ms_s[0])[k], v0 = ((float4*)am_s[0])[k];
        float4 s1 = ((float4*)ms_s[1])[k], v1 = ((float4*)am_s[1])[k];
        float4 s2 = ((float4*)ms_s[2])[k], v2 = ((float4*)am_s[2])[k];
        float4 s3 = ((float4*)ms_s[3])[k], v3 = ((float4*)am_s[3])[k];
        a0 += s0.x * u.x + s0.y * u.y + s0.z * u.z + s0.w * u.w
            + v0.x * w.x + v0.y * w.y + v0.z * w.z + v0.w * w.w;
        a1 += s1.x * u.x + s1.y * u.y + s1.z * u.z + s1.w * u.w
            + v1.x * w.x + v1.y * w.y + v1.z * w.z + v1.w * w.w;
        a2 += s2.x * u.x + s2.y * u.y + s2.z * u.z + s2.w * u.w
            + v2.x * w.x + v2.y * w.y + v2.z * w.z + v2.w * w.w;
        a3 += s3.x * u.x + s3.y * u.y + s3.z * u.z + s3.w * u.w
            + v3.x * w.x + v3.y * w.y + v3.z * w.z + v3.w * w.w;
    }
    float bias = Ub[d] + Wb[d];
    float accs[4] = {a0, a1, a2, a3};
    #pragma unroll
    for (int mi = 0; mi < 4; mi++) {
        float g = 1.0f / (1.0f + __expf(-(accs[mi] + bias)));
        outM[(m0 + mi) * DD + d] = (1.0f - g) * ms_s[mi][d] + g * am_s[mi][d];
    }
}

extern "C" void kernel_launch(void* const* d_in, const int* in_sizes, int n_in,
                              void* d_out, int out_size)
{
    const float* qg   = (const float*)d_in[0];
    const float* memg = (const float*)d_in[1];
    const float* Uw   = (const float*)d_in[2];
    const float* Ub   = (const float*)d_in[3];
    const float* Ww   = (const float*)d_in[4];
    const float* Wb   = (const float*)d_in[5];

    int N  = in_sizes[0] / DD;
    int NS = (N + 8191) / 8192;
    int NB = N / TOK;

    float* outO = (float*)d_out;
    float* outA = outO + (size_t)N * 2 * DD;
    float* outM = outA + (size_t)N * MM;

    cudaFuncSetAttribute((const void*)k1_main,
                         cudaFuncAttributeMaxDynamicSharedMemorySize, SMEM_TOTAL);

    k0_prep<<<128, 256>>>(memg);
    k1_main<<<NB, 256, SMEM_TOTAL>>>(qg, outO, outA, N);
    k3_sparse<<<dim3(NS, MM), 512>>>(qg, N, NS, NB);
    k4a_am<<<MM, DD>>>(NS);
    k4b_gate<<<dim3(4, 16), 128>>>(memg, Uw, Ub, Ww, Wb, outM);
}